// round 3
// baseline (speedup 1.0000x reference)
#include <cuda_runtime.h>
#include <cstdint>
#include <cfloat>

// Problem constants (fixed by the dataset)
constexpr int Bv  = 16;      // batch
constexpr int Nv  = 16384;   // pixels
constexpr int Dv  = 64;      // embed dim
constexpr int Kv  = 64;      // templates
constexpr int D4v = Dv / 4;  // float4 chunks per vector (16)
constexpr int PITCH = D4v + 1; // padded smem pitch in float4 -> conflict-free
constexpr float EPS = 1e-3f; // near-tie refinement margin (>> fp32 dist error ~1e-5)

__global__ __launch_bounds__(64, 8)
void osc_kernel(const float4* __restrict__ xg,     // frame_embeddings [B,N,D] f32
                const float4* __restrict__ tg,     // templates        [K,N,D] f32
                const int*    __restrict__ tcls,   // template_classes [K] int32
                float* __restrict__ out)
{
    __shared__ float4 ts[Kv * PITCH];
    __shared__ float4 xs[Bv * PITCH];
    __shared__ float  t2s[Kv];
    __shared__ float  x2s[Bv];
    __shared__ float  clsf[Kv];
    __shared__ float  rv[Bv][16];
    __shared__ float  bestvs[Bv];
    __shared__ unsigned long long refined[Bv];

    const int n   = blockIdx.x;
    const int tid = threadIdx.x;

    // ---- stage tiles (coalesced 256B rows) ----
#pragma unroll
    for (int i = 0; i < 16; ++i) {
        int idx = tid + i * 64;
        int k   = idx >> 4;
        int d4  = idx & 15;
        ts[k * PITCH + d4] = tg[((size_t)k * Nv + n) * D4v + d4];
    }
#pragma unroll
    for (int i = 0; i < 4; ++i) {
        int idx = tid + i * 64;
        int b   = idx >> 4;
        int d4  = idx & 15;
        xs[b * PITCH + d4] = xg[((size_t)b * Nv + n) * D4v + d4];
    }
    clsf[tid] = (float)tcls[tid];
    __syncthreads();

    // ---- norms ----
    {
        float s0 = 0.f, s1 = 0.f, s2 = 0.f, s3 = 0.f;
#pragma unroll
        for (int d4 = 0; d4 < D4v; ++d4) {
            float4 v = ts[tid * PITCH + d4];
            s0 = fmaf(v.x, v.x, s0); s1 = fmaf(v.y, v.y, s1);
            s2 = fmaf(v.z, v.z, s2); s3 = fmaf(v.w, v.w, s3);
        }
        t2s[tid] = (s0 + s1) + (s2 + s3);
    }
    if (tid < Bv) {
        float s0 = 0.f, s1 = 0.f, s2 = 0.f, s3 = 0.f;
#pragma unroll
        for (int d4 = 0; d4 < D4v; ++d4) {
            float4 v = xs[tid * PITCH + d4];
            s0 = fmaf(v.x, v.x, s0); s1 = fmaf(v.y, v.y, s1);
            s2 = fmaf(v.z, v.z, s2); s3 = fmaf(v.w, v.w, s3);
        }
        x2s[tid] = (s0 + s1) + (s2 + s3);
        refined[tid] = 0xFFFFFFFFFFFFFFFFULL;
    }
    __syncthreads();

    // ---- Phase A: 4x4 register-tile fp32 dot products ----
    // thread covers b in {c, c+4, c+8, c+12}, k in {r, r+16, r+32, r+48}
    const int c = tid & 3;
    const int r = tid >> 2;

    float acc[4][4];
#pragma unroll
    for (int i = 0; i < 4; ++i)
#pragma unroll
        for (int j = 0; j < 4; ++j) acc[i][j] = 0.f;

#pragma unroll 4
    for (int d4 = 0; d4 < D4v; ++d4) {
        float4 xv[4], tv[4];
#pragma unroll
        for (int i = 0; i < 4; ++i) xv[i] = xs[(c + 4 * i) * PITCH + d4];
#pragma unroll
        for (int j = 0; j < 4; ++j) tv[j] = ts[(r + 16 * j) * PITCH + d4];
#pragma unroll
        for (int i = 0; i < 4; ++i)
#pragma unroll
            for (int j = 0; j < 4; ++j) {
                acc[i][j] = fmaf(xv[i].x, tv[j].x, acc[i][j]);
                acc[i][j] = fmaf(xv[i].y, tv[j].y, acc[i][j]);
                acc[i][j] = fmaf(xv[i].z, tv[j].z, acc[i][j]);
                acc[i][j] = fmaf(xv[i].w, tv[j].w, acc[i][j]);
            }
    }

    // per-thread min over its 4 k's for each of its 4 b's (value only)
#pragma unroll
    for (int i = 0; i < 4; ++i) {
        const int   b   = c + 4 * i;
        const float bx2 = x2s[b];
        float bestv = FLT_MAX;
#pragma unroll
        for (int j = 0; j < 4; ++j) {
            const float d = bx2 + t2s[r + 16 * j] - 2.0f * acc[i][j];
            bestv = fminf(bestv, d);
        }
        rv[b][r] = bestv;
    }
    __syncthreads();

    // final fp32 min per b
    if (tid < Bv) {
        float bestv = rv[tid][0];
#pragma unroll
        for (int q = 1; q < 16; ++q) bestv = fminf(bestv, rv[tid][q]);
        bestvs[tid] = bestv;
    }
    __syncthreads();

    // ---- Phase B: exact fp64 refinement of near-tie candidates ----
    // For each (b,k) this thread owns with fp32 dist <= min + EPS, recompute
    // the distance exactly in fp64 (direct sum of squared diffs), round to
    // fp32, and take argmin with first-occurrence (lowest-k) tie-break via a
    // packed (float_bits << 6 | k) atomicMin key — mimics jnp.argmin over
    // fp32 values including its exact-tie rule.
#pragma unroll
    for (int i = 0; i < 4; ++i) {
        const int   b   = c + 4 * i;
        const float bx2 = x2s[b];
        const float lim = bestvs[b] + EPS;
#pragma unroll
        for (int j = 0; j < 4; ++j) {
            const int   k = r + 16 * j;
            const float d = bx2 + t2s[k] - 2.0f * acc[i][j];
            if (d <= lim) {
                double dd = 0.0;
#pragma unroll
                for (int d4 = 0; d4 < D4v; ++d4) {
                    float4 xv = xs[b * PITCH + d4];
                    float4 tv = ts[k * PITCH + d4];
                    double e0 = (double)xv.x - (double)tv.x;
                    double e1 = (double)xv.y - (double)tv.y;
                    double e2 = (double)xv.z - (double)tv.z;
                    double e3 = (double)xv.w - (double)tv.w;
                    dd = fma(e0, e0, dd);
                    dd = fma(e1, e1, dd);
                    dd = fma(e2, e2, dd);
                    dd = fma(e3, e3, dd);
                }
                const float df = (float)dd;           // round exact -> fp32
                const unsigned long long key =
                    ((unsigned long long)__float_as_uint(df) << 6) |
                    (unsigned long long)k;
                atomicMin(&refined[b], key);
            }
        }
    }
    __syncthreads();

    // ---- outputs ----
    if (tid < Bv) {
        const unsigned long long key = refined[tid];
        const int   bestk = (int)(key & 63ULL);
        const float bestv = __uint_as_float((unsigned int)(key >> 6));
        const size_t BN = (size_t)Bv * Nv;
        const size_t o  = (size_t)tid * Nv + n;
        out[o]           = (bestv <= 0.5f) ? 1.0f : 0.0f;  // mask @ 0.5
        out[BN + o]      = (bestv <= 1.0f) ? 1.0f : 0.0f;  // mask @ 1.0
        out[2 * BN + o]  = bestv;                          // min_dists
        out[3 * BN + o]  = clsf[bestk];                    // pred_classes
    }
}

extern "C" void kernel_launch(void* const* d_in, const int* in_sizes, int n_in,
                              void* d_out, int out_size)
{
    const float4* frame = (const float4*)d_in[0];   // [16,16384,64] f32
    const float4* tmpl  = (const float4*)d_in[1];   // [64,16384,64] f32
    const int*    tcls  = (const int*)d_in[2];      // [64] int32
    float*        out   = (float*)d_out;

    osc_kernel<<<Nv, 64>>>(frame, tmpl, tcls, out);
}

// round 4
// speedup vs baseline: 43.3776x; 43.3776x over previous
#include <cuda_runtime.h>
#include <cstdint>
#include <cfloat>

// Problem constants (fixed by the dataset)
constexpr int Bv  = 16;      // batch
constexpr int Nv  = 16384;   // pixels
constexpr int Dv  = 64;      // embed dim
constexpr int Kv  = 64;      // templates
constexpr int D4v = Dv / 4;  // float4 chunks per vector (16)
constexpr int PITCH = D4v + 1; // padded smem pitch in float4 -> conflict-free
constexpr float EPS = 1e-3f; // near-tie margin (>> fp32 dist error ~1e-5)

__global__ __launch_bounds__(64, 8)
void osc_kernel(const float4* __restrict__ xg,     // frame_embeddings [B,N,D] f32
                const float4* __restrict__ tg,     // templates        [K,N,D] f32
                const int*    __restrict__ tcls,   // template_classes [K] int32
                float* __restrict__ out)
{
    __shared__ float4 ts[Kv * PITCH];
    __shared__ float4 xs[Bv * PITCH];
    __shared__ float  t2s[Kv];
    __shared__ float  x2s[Bv];
    __shared__ float  clsf[Kv];
    __shared__ float  rv[Bv][16];
    __shared__ int    ri[Bv][16];
    __shared__ float  bestvs[Bv];
    __shared__ int    bestks[Bv];
    __shared__ int    cnt[Bv];
    __shared__ unsigned long long refined[Bv];

    const int n   = blockIdx.x;
    const int tid = threadIdx.x;

    // ---- stage tiles (coalesced 256B rows) ----
#pragma unroll
    for (int i = 0; i < 16; ++i) {
        int idx = tid + i * 64;
        int k   = idx >> 4;
        int d4  = idx & 15;
        ts[k * PITCH + d4] = tg[((size_t)k * Nv + n) * D4v + d4];
    }
#pragma unroll
    for (int i = 0; i < 4; ++i) {
        int idx = tid + i * 64;
        int b   = idx >> 4;
        int d4  = idx & 15;
        xs[b * PITCH + d4] = xg[((size_t)b * Nv + n) * D4v + d4];
    }
    clsf[tid] = (float)tcls[tid];
    __syncthreads();

    // ---- norms ----
    {
        float s0 = 0.f, s1 = 0.f, s2 = 0.f, s3 = 0.f;
#pragma unroll
        for (int d4 = 0; d4 < D4v; ++d4) {
            float4 v = ts[tid * PITCH + d4];
            s0 = fmaf(v.x, v.x, s0); s1 = fmaf(v.y, v.y, s1);
            s2 = fmaf(v.z, v.z, s2); s3 = fmaf(v.w, v.w, s3);
        }
        t2s[tid] = (s0 + s1) + (s2 + s3);
    }
    if (tid < Bv) {
        float s0 = 0.f, s1 = 0.f, s2 = 0.f, s3 = 0.f;
#pragma unroll
        for (int d4 = 0; d4 < D4v; ++d4) {
            float4 v = xs[tid * PITCH + d4];
            s0 = fmaf(v.x, v.x, s0); s1 = fmaf(v.y, v.y, s1);
            s2 = fmaf(v.z, v.z, s2); s3 = fmaf(v.w, v.w, s3);
        }
        x2s[tid] = (s0 + s1) + (s2 + s3);
        cnt[tid]     = 0;
        refined[tid] = 0xFFFFFFFFFFFFFFFFULL;
    }
    __syncthreads();

    // ---- Phase A: 4x4 register-tile fp32 dot products ----
    // thread covers b in {c, c+4, c+8, c+12}, k in {r, r+16, r+32, r+48}
    const int c = tid & 3;
    const int r = tid >> 2;

    float acc[4][4];
#pragma unroll
    for (int i = 0; i < 4; ++i)
#pragma unroll
        for (int j = 0; j < 4; ++j) acc[i][j] = 0.f;

#pragma unroll 4
    for (int d4 = 0; d4 < D4v; ++d4) {
        float4 xv[4], tv[4];
#pragma unroll
        for (int i = 0; i < 4; ++i) xv[i] = xs[(c + 4 * i) * PITCH + d4];
#pragma unroll
        for (int j = 0; j < 4; ++j) tv[j] = ts[(r + 16 * j) * PITCH + d4];
#pragma unroll
        for (int i = 0; i < 4; ++i)
#pragma unroll
            for (int j = 0; j < 4; ++j) {
                acc[i][j] = fmaf(xv[i].x, tv[j].x, acc[i][j]);
                acc[i][j] = fmaf(xv[i].y, tv[j].y, acc[i][j]);
                acc[i][j] = fmaf(xv[i].z, tv[j].z, acc[i][j]);
                acc[i][j] = fmaf(xv[i].w, tv[j].w, acc[i][j]);
            }
    }

    // Convert dot products to distances in-place; per-thread min+argmin.
#pragma unroll
    for (int i = 0; i < 4; ++i) {
        const int   b   = c + 4 * i;
        const float bx2 = x2s[b];
        float bestv = FLT_MAX;
        int   bestk = Kv;
#pragma unroll
        for (int j = 0; j < 4; ++j) {
            const int k = r + 16 * j;
            const float d = bx2 + t2s[k] - 2.0f * acc[i][j];
            acc[i][j] = d;                         // keep for candidate pass
            if (d < bestv) { bestv = d; bestk = k; } // j ascending => first-min
        }
        rv[b][r] = bestv;
        ri[b][r] = bestk;
    }
    __syncthreads();

    // ---- fp32 min + argmin per b (threads 0..15) ----
    if (tid < Bv) {
        float bestv = rv[tid][0];
        int   bestk = ri[tid][0];
#pragma unroll
        for (int q = 1; q < 16; ++q) {
            const float v = rv[tid][q];
            const int   k = ri[tid][q];
            if (v < bestv || (v == bestv && k < bestk)) { bestv = v; bestk = k; }
        }
        bestvs[tid] = bestv;
        bestks[tid] = bestk;
    }
    __syncthreads();

    // ---- count near-tie candidates per b ----
#pragma unroll
    for (int i = 0; i < 4; ++i) {
        const int b = c + 4 * i;
        const float lim = bestvs[b] + EPS;
        int local = 0;
#pragma unroll
        for (int j = 0; j < 4; ++j) local += (acc[i][j] <= lim) ? 1 : 0;
        if (local) atomicAdd(&cnt[b], local);
    }
    __syncthreads();

    // ---- Phase B (RARE): exact fp64 refinement, only for contested b ----
#pragma unroll
    for (int i = 0; i < 4; ++i) {
        const int b = c + 4 * i;
        if (cnt[b] < 2) continue;                 // uncontested: skip fp64
        const float lim = bestvs[b] + EPS;
#pragma unroll
        for (int j = 0; j < 4; ++j) {
            if (acc[i][j] > lim) continue;
            const int k = r + 16 * j;
            double dd = 0.0;
            for (int d4 = 0; d4 < D4v; ++d4) {
                float4 xv = xs[b * PITCH + d4];
                float4 tv = ts[k * PITCH + d4];
                double e0 = (double)xv.x - (double)tv.x;
                double e1 = (double)xv.y - (double)tv.y;
                double e2 = (double)xv.z - (double)tv.z;
                double e3 = (double)xv.w - (double)tv.w;
                dd = fma(e0, e0, dd);
                dd = fma(e1, e1, dd);
                dd = fma(e2, e2, dd);
                dd = fma(e3, e3, dd);
            }
            const float df = (float)dd;           // exact -> fp32
            const unsigned long long key =
                ((unsigned long long)__float_as_uint(df) << 6) |
                (unsigned long long)k;
            atomicMin(&refined[b], key);
        }
    }
    __syncthreads();

    // ---- outputs ----
    if (tid < Bv) {
        float bestv;
        int   bestk;
        if (cnt[tid] >= 2) {
            const unsigned long long key = refined[tid];
            bestk = (int)(key & 63ULL);
            bestv = __uint_as_float((unsigned int)(key >> 6));
        } else {
            bestv = bestvs[tid];
            bestk = bestks[tid];
        }
        const size_t BN = (size_t)Bv * Nv;
        const size_t o  = (size_t)tid * Nv + n;
        out[o]           = (bestv <= 0.5f) ? 1.0f : 0.0f;  // mask @ 0.5
        out[BN + o]      = (bestv <= 1.0f) ? 1.0f : 0.0f;  // mask @ 1.0
        out[2 * BN + o]  = bestv;                          // min_dists
        out[3 * BN + o]  = clsf[bestk];                    // pred_classes
    }
}

extern "C" void kernel_launch(void* const* d_in, const int* in_sizes, int n_in,
                              void* d_out, int out_size)
{
    const float4* frame = (const float4*)d_in[0];   // [16,16384,64] f32
    const float4* tmpl  = (const float4*)d_in[1];   // [64,16384,64] f32
    const int*    tcls  = (const int*)d_in[2];      // [64] int32
    float*        out   = (float*)d_out;

    osc_kernel<<<Nv, 64>>>(frame, tmpl, tcls, out);
}